// round 4
// baseline (speedup 1.0000x reference)
#include <cuda_runtime.h>
#include <cstdint>

// ============================================================================
// MTSCNN: 64 per-channel conv extractors + (folded) linear tail.
// f32x2 packed-math version: one thread = (channel c, batch pair), computing
// two samples per instruction via fma.rn.f32x2 / mul.rn.f32x2.
//
// Algebra exploited (validated at 2.4e-7 rel_err by the scalar R3 kernel):
//  * No activation after `feat` -> per-channel FC (32->64->32->1) and the
//    detection head (64->64->1) fold into one [64x32] weight W + scalar C0.
//  * maxpool tail-trim: conv2 l=4 dead -> p1[*][6], t[14..15] dead.
//
// leaky+maxpool fused: max(leaky(a),leaky(b)) = max(max(a,.05a),max(b,.05b));
// the .05 multiplies are packed (fma pipe), the max tree is FMNMX (alu pipe).
// ============================================================================

typedef unsigned long long u64;

__device__ __forceinline__ u64 pk2(float lo, float hi) {
    u64 d;
    asm("mov.b64 %0, {%1, %2};" : "=l"(d)
        : "r"(__float_as_uint(lo)), "r"(__float_as_uint(hi)));
    return d;
}
__device__ __forceinline__ void upk2(u64 d, float& lo, float& hi) {
    unsigned int l, h;
    asm("mov.b64 {%0, %1}, %2;" : "=r"(l), "=r"(h) : "l"(d));
    lo = __uint_as_float(l);
    hi = __uint_as_float(h);
}
__device__ __forceinline__ u64 ffma2(u64 a, u64 b, u64 c) {
    u64 d;
    asm("fma.rn.f32x2 %0, %1, %2, %3;" : "=l"(d) : "l"(a), "l"(b), "l"(c));
    return d;
}
__device__ __forceinline__ u64 fmul2(u64 a, u64 b) {
    u64 d;
    asm("mul.rn.f32x2 %0, %1, %2;" : "=l"(d) : "l"(a), "l"(b));
    return d;
}
// fused: per-half max(leaky(a), leaky(b)) for packed a,b; C = {0.05,0.05}
__device__ __forceinline__ u64 lpool2(u64 a, u64 b, u64 C) {
    u64 sa = fmul2(a, C);
    u64 sb = fmul2(b, C);
    float a0, a1, b0, b1, s0, s1, t0, t1;
    upk2(a, a0, a1); upk2(sa, s0, s1);
    upk2(b, b0, b1); upk2(sb, t0, t1);
    float r0 = fmaxf(fmaxf(a0, s0), fmaxf(b0, t0));
    float r1 = fmaxf(fmaxf(a1, s1), fmaxf(b1, t1));
    return pk2(r0, r1);
}

// ---- precomputed / repacked parameter storage (channel-last) ----
__device__ float g_w1t[24 * 64];   // [(o*3+k)*64 + c]
__device__ float g_b1t[8 * 64];    // [o*64 + c]
__device__ float g_w2t[384 * 64];  // [((o2*8+o)*3+k)*64 + c]
__device__ float g_b2t[16 * 64];   // [o2*64 + c]
__device__ float g_Wt[32 * 64];    // [f*64 + c]  (folded linear tail)
__device__ float g_r2[64 * 64];    // scratch: fw3_c @ fw2_c   [c*64 + j]
__device__ float g_u[64];          // dw2 @ dw1
__device__ float g_C0[1];

// ============================================================================
// pre1: repack conv weights channel-last; compute r2[c][j] and u[c].
// ============================================================================
__global__ void mtscnn_pre1(const float* __restrict__ w1, const float* __restrict__ b1,
                            const float* __restrict__ w2, const float* __restrict__ b2,
                            const float* __restrict__ fw2, const float* __restrict__ fw3,
                            const float* __restrict__ dw1, const float* __restrict__ dw2) {
    int tid = blockIdx.x * blockDim.x + threadIdx.x;
    if (tid < 4096) {
        int c = tid >> 6, j = tid & 63;
        float s = 0.f;
#pragma unroll
        for (int i = 0; i < 32; i++)
            s += fw3[c * 32 + i] * fw2[c * 2048 + i * 64 + j];
        g_r2[c * 64 + j] = s;
    } else if (tid < 4160) {
        int c = tid - 4096;
        float s = 0.f;
#pragma unroll
        for (int j = 0; j < 64; j++) s += dw2[j] * dw1[j * 64 + c];
        g_u[c] = s;
    } else if (tid < 4160 + 1536) {
        int i = tid - 4160;            // i = c*24 + (o*3+k)
        int c = i / 24, r = i % 24;
        g_w1t[r * 64 + c] = w1[i];
    } else if (tid < 4160 + 1536 + 512) {
        int i = tid - (4160 + 1536);   // i = c*8 + o
        int c = i >> 3, o = i & 7;
        g_b1t[o * 64 + c] = b1[i];
    } else if (tid < 4160 + 1536 + 512 + 24576) {
        int i = tid - (4160 + 1536 + 512);  // i = c*384 + (o2*24 + o*3 + k)
        int c = i / 384, r = i % 384;
        g_w2t[r * 64 + c] = w2[i];
    } else if (tid < 4160 + 1536 + 512 + 24576 + 1024) {
        int i = tid - (4160 + 1536 + 512 + 24576);  // i = c*16 + o2
        int c = i >> 4, o2 = i & 15;
        g_b2t[o2 * 64 + c] = b2[i];
    }
}

// ============================================================================
// pre2: fold the linear tail.
//   W[c][f] = u[c] * sum_j r2[c][j] * fw1[c][j][f]
//   C0      = sum_c u[c]*b_eff[c] + dw2.db1 + db2
//   b_eff[c] = sum_j r2[c][j]*fb1[c][j] + sum_i fw3[c][i]*fb2[c][i] + fb3[c]
// ============================================================================
__global__ void mtscnn_pre2(const float* __restrict__ fw1, const float* __restrict__ fb1,
                            const float* __restrict__ fb2, const float* __restrict__ fb3,
                            const float* __restrict__ fw3,
                            const float* __restrict__ db1, const float* __restrict__ dw2,
                            const float* __restrict__ db2) {
    __shared__ float sh_beff[64];
    int tid = threadIdx.x;
    for (int e = tid; e < 2048; e += blockDim.x) {
        int c = e >> 5, f = e & 31;
        float s = 0.f;
#pragma unroll
        for (int j = 0; j < 64; j++)
            s += g_r2[c * 64 + j] * fw1[c * 2048 + j * 32 + f];
        g_Wt[f * 64 + c] = g_u[c] * s;
    }
    if (tid < 64) {
        int c = tid;
        float s = 0.f;
#pragma unroll
        for (int j = 0; j < 64; j++) s += g_r2[c * 64 + j] * fb1[c * 64 + j];
#pragma unroll
        for (int i = 0; i < 32; i++) s += fw3[c * 32 + i] * fb2[c * 32 + i];
        sh_beff[c] = s + fb3[c];
    }
    __syncthreads();
    if (tid == 0) {
        float C = db2[0];
        for (int j = 0; j < 64; j++) C += dw2[j] * db1[j];
        for (int c = 0; c < 64; c++) C += g_u[c] * sh_beff[c];
        g_C0[0] = C;
    }
}

// ============================================================================
// main: thread = (channel c, batch pair). Packed f32x2: lo = sample 2p, hi = 2p+1.
// Block = 128 threads = 2 pairs x 64 channels -> 4 samples per block.
// ============================================================================
__global__ __launch_bounds__(128, 2) void mtscnn_main(const float* __restrict__ x,
                                                      float* __restrict__ out) {
    const int c  = threadIdx.x & 63;
    const int pl = threadIdx.x >> 6;                      // which pair in block
    const long long pairIdx = (long long)blockIdx.x * 2 + pl;
    const size_t base = (size_t)pairIdx * 2048 + c;       // 1024 floats per sample

    const u64 C05 = pk2(0.05f, 0.05f);

    // ---- load input taps (t[14..15] dead after pool-trim analysis) ----
    u64 t[14];
#pragma unroll
    for (int i = 0; i < 14; i++) {
        float lo = x[base + i * 64];
        float hi = x[base + 1024 + i * 64];
        t[i] = pk2(lo, hi);
    }

    // ---- conv1 (K=3, valid) + fused leaky+maxpool2: pooled outputs 0..5 ----
    u64 p1[8][6];
#pragma unroll
    for (int o = 0; o < 8; o++) {
        float w0 = g_w1t[(o * 3 + 0) * 64 + c];
        float w1 = g_w1t[(o * 3 + 1) * 64 + c];
        float w2 = g_w1t[(o * 3 + 2) * 64 + c];
        float bb = g_b1t[o * 64 + c];
        u64 W0 = pk2(w0, w0), W1 = pk2(w1, w1), W2 = pk2(w2, w2), BB = pk2(bb, bb);
#pragma unroll
        for (int j = 0; j < 6; j++) {
            u64 hA = ffma2(W0, t[2 * j],     ffma2(W1, t[2 * j + 1], ffma2(W2, t[2 * j + 2], BB)));
            u64 hB = ffma2(W0, t[2 * j + 1], ffma2(W1, t[2 * j + 2], ffma2(W2, t[2 * j + 3], BB)));
            p1[o][j] = lpool2(hA, hB, C05);
        }
    }

    // ---- conv2 (8->16, K=3) + fused leaky+maxpool2 (l=4 dead) + folded dot ----
    float slo = 0.f, shi = 0.f;
#pragma unroll 1
    for (int o2 = 0; o2 < 16; o2++) {
        float bb = g_b2t[o2 * 64 + c];
        u64 BB = pk2(bb, bb);
        u64 a0 = BB, a1 = BB, a2 = BB, a3 = BB;
#pragma unroll
        for (int o = 0; o < 8; o++) {
#pragma unroll
            for (int k = 0; k < 3; k++) {
                float w = g_w2t[((o2 * 8 + o) * 3 + k) * 64 + c];
                u64 W = pk2(w, w);
                a0 = ffma2(W, p1[o][k],     a0);
                a1 = ffma2(W, p1[o][k + 1], a1);
                a2 = ffma2(W, p1[o][k + 2], a2);
                a3 = ffma2(W, p1[o][k + 3], a3);
            }
        }
        u64 q0 = lpool2(a0, a1, C05);
        u64 q1 = lpool2(a2, a3, C05);
        float q0lo, q0hi, q1lo, q1hi;
        upk2(q0, q0lo, q0hi);
        upk2(q1, q1lo, q1hi);
        float Wf0 = g_Wt[(o2 * 2 + 0) * 64 + c];
        float Wf1 = g_Wt[(o2 * 2 + 1) * 64 + c];
        slo = fmaf(q0lo, Wf0, fmaf(q1lo, Wf1, slo));
        shi = fmaf(q0hi, Wf0, fmaf(q1hi, Wf1, shi));
    }

    // ---- reduce over the 64 channels (2 warps per pair) ----
#pragma unroll
    for (int off = 16; off > 0; off >>= 1) {
        slo += __shfl_down_sync(0xffffffffu, slo, off);
        shi += __shfl_down_sync(0xffffffffu, shi, off);
    }
    __shared__ float red[4][2];
    int w = threadIdx.x >> 5;
    if ((threadIdx.x & 31) == 0) {
        red[w][0] = slo;
        red[w][1] = shi;
    }
    __syncthreads();
    if ((threadIdx.x & 63) == 0) {
        float C0 = g_C0[0];
        long long b0 = pairIdx * 2;
        out[b0]     = red[pl * 2][0] + red[pl * 2 + 1][0] + C0;
        out[b0 + 1] = red[pl * 2][1] + red[pl * 2 + 1][1] + C0;
    }
}

// ============================================================================
// launch
// ============================================================================
extern "C" void kernel_launch(void* const* d_in, const int* in_sizes, int n_in,
                              void* d_out, int out_size) {
    const float* x   = (const float*)d_in[0];
    const float* w1  = (const float*)d_in[1];
    const float* b1  = (const float*)d_in[2];
    const float* w2  = (const float*)d_in[3];
    const float* b2  = (const float*)d_in[4];
    const float* fw1 = (const float*)d_in[5];
    const float* fb1 = (const float*)d_in[6];
    const float* fw2 = (const float*)d_in[7];
    const float* fb2 = (const float*)d_in[8];
    const float* fw3 = (const float*)d_in[9];
    const float* fb3 = (const float*)d_in[10];
    const float* dw1 = (const float*)d_in[11];
    const float* db1 = (const float*)d_in[12];
    const float* dw2 = (const float*)d_in[13];
    const float* db2 = (const float*)d_in[14];
    float* out = (float*)d_out;

    mtscnn_pre1<<<125, 256>>>(w1, b1, w2, b2, fw2, fw3, dw1, dw2);
    mtscnn_pre2<<<1, 1024>>>(fw1, fb1, fb2, fb3, fw3, db1, dw2, db2);

    int B = in_sizes[0] / 1024;          // 32768 (x is [B,1,16,8,8])
    int nPairs = B / 2;                  // 2 samples per thread
    int nBlocks = nPairs / 2;            // 2 pairs per 128-thread block
    mtscnn_main<<<nBlocks, 128>>>(x, out);
}

// round 5
// speedup vs baseline: 1.0023x; 1.0023x over previous
#include <cuda_runtime.h>
#include <cstdint>

// ============================================================================
// MTSCNN: 64 per-channel conv extractors + (folded) linear tail.
// f32x2 packed-math version: one thread = (channel c, batch pair), computing
// two samples per instruction via fma.rn.f32x2 / mul.rn.f32x2.
//
// Algebra exploited (validated at 2.4e-7 rel_err by the scalar R3 kernel):
//  * No activation after `feat` -> per-channel FC (32->64->32->1) and the
//    detection head (64->64->1) fold into one [64x32] weight W + scalar C0.
//  * maxpool tail-trim: conv2 l=4 dead -> p1[*][6], t[14..15] dead.
//
// leaky+maxpool fused: max(leaky(a),leaky(b)) = max(max(a,.05a),max(b,.05b));
// the .05 multiplies are packed (fma pipe), the max tree is FMNMX (alu pipe).
// ============================================================================

typedef unsigned long long u64;

__device__ __forceinline__ u64 pk2(float lo, float hi) {
    u64 d;
    asm("mov.b64 %0, {%1, %2};" : "=l"(d)
        : "r"(__float_as_uint(lo)), "r"(__float_as_uint(hi)));
    return d;
}
__device__ __forceinline__ void upk2(u64 d, float& lo, float& hi) {
    unsigned int l, h;
    asm("mov.b64 {%0, %1}, %2;" : "=r"(l), "=r"(h) : "l"(d));
    lo = __uint_as_float(l);
    hi = __uint_as_float(h);
}
__device__ __forceinline__ u64 ffma2(u64 a, u64 b, u64 c) {
    u64 d;
    asm("fma.rn.f32x2 %0, %1, %2, %3;" : "=l"(d) : "l"(a), "l"(b), "l"(c));
    return d;
}
__device__ __forceinline__ u64 fmul2(u64 a, u64 b) {
    u64 d;
    asm("mul.rn.f32x2 %0, %1, %2;" : "=l"(d) : "l"(a), "l"(b));
    return d;
}
// fused: per-half max(leaky(a), leaky(b)) for packed a,b; C = {0.05,0.05}
__device__ __forceinline__ u64 lpool2(u64 a, u64 b, u64 C) {
    u64 sa = fmul2(a, C);
    u64 sb = fmul2(b, C);
    float a0, a1, b0, b1, s0, s1, t0, t1;
    upk2(a, a0, a1); upk2(sa, s0, s1);
    upk2(b, b0, b1); upk2(sb, t0, t1);
    float r0 = fmaxf(fmaxf(a0, s0), fmaxf(b0, t0));
    float r1 = fmaxf(fmaxf(a1, s1), fmaxf(b1, t1));
    return pk2(r0, r1);
}

// ---- precomputed / repacked parameter storage (channel-last) ----
__device__ float g_w1t[24 * 64];   // [(o*3+k)*64 + c]
__device__ float g_b1t[8 * 64];    // [o*64 + c]
__device__ float g_w2t[384 * 64];  // [((o2*8+o)*3+k)*64 + c]
__device__ float g_b2t[16 * 64];   // [o2*64 + c]
__device__ float g_Wt[32 * 64];    // [f*64 + c]  (folded linear tail)
__device__ float g_r2[64 * 64];    // scratch: fw3_c @ fw2_c   [c*64 + j]
__device__ float g_u[64];          // dw2 @ dw1
__device__ float g_C0[1];

// ============================================================================
// pre1: repack conv weights channel-last; compute r2[c][j] and u[c].
// ============================================================================
__global__ void mtscnn_pre1(const float* __restrict__ w1, const float* __restrict__ b1,
                            const float* __restrict__ w2, const float* __restrict__ b2,
                            const float* __restrict__ fw2, const float* __restrict__ fw3,
                            const float* __restrict__ dw1, const float* __restrict__ dw2) {
    int tid = blockIdx.x * blockDim.x + threadIdx.x;
    if (tid < 4096) {
        int c = tid >> 6, j = tid & 63;
        float s = 0.f;
#pragma unroll
        for (int i = 0; i < 32; i++)
            s += fw3[c * 32 + i] * fw2[c * 2048 + i * 64 + j];
        g_r2[c * 64 + j] = s;
    } else if (tid < 4160) {
        int c = tid - 4096;
        float s = 0.f;
#pragma unroll
        for (int j = 0; j < 64; j++) s += dw2[j] * dw1[j * 64 + c];
        g_u[c] = s;
    } else if (tid < 4160 + 1536) {
        int i = tid - 4160;            // i = c*24 + (o*3+k)
        int c = i / 24, r = i % 24;
        g_w1t[r * 64 + c] = w1[i];
    } else if (tid < 4160 + 1536 + 512) {
        int i = tid - (4160 + 1536);   // i = c*8 + o
        int c = i >> 3, o = i & 7;
        g_b1t[o * 64 + c] = b1[i];
    } else if (tid < 4160 + 1536 + 512 + 24576) {
        int i = tid - (4160 + 1536 + 512);  // i = c*384 + (o2*24 + o*3 + k)
        int c = i / 384, r = i % 384;
        g_w2t[r * 64 + c] = w2[i];
    } else if (tid < 4160 + 1536 + 512 + 24576 + 1024) {
        int i = tid - (4160 + 1536 + 512 + 24576);  // i = c*16 + o2
        int c = i >> 4, o2 = i & 15;
        g_b2t[o2 * 64 + c] = b2[i];
    }
}

// ============================================================================
// pre2: fold the linear tail.
//   W[c][f] = u[c] * sum_j r2[c][j] * fw1[c][j][f]
//   C0      = sum_c u[c]*b_eff[c] + dw2.db1 + db2
//   b_eff[c] = sum_j r2[c][j]*fb1[c][j] + sum_i fw3[c][i]*fb2[c][i] + fb3[c]
// ============================================================================
__global__ void mtscnn_pre2(const float* __restrict__ fw1, const float* __restrict__ fb1,
                            const float* __restrict__ fb2, const float* __restrict__ fb3,
                            const float* __restrict__ fw3,
                            const float* __restrict__ db1, const float* __restrict__ dw2,
                            const float* __restrict__ db2) {
    __shared__ float sh_beff[64];
    int tid = threadIdx.x;
    for (int e = tid; e < 2048; e += blockDim.x) {
        int c = e >> 5, f = e & 31;
        float s = 0.f;
#pragma unroll
        for (int j = 0; j < 64; j++)
            s += g_r2[c * 64 + j] * fw1[c * 2048 + j * 32 + f];
        g_Wt[f * 64 + c] = g_u[c] * s;
    }
    if (tid < 64) {
        int c = tid;
        float s = 0.f;
#pragma unroll
        for (int j = 0; j < 64; j++) s += g_r2[c * 64 + j] * fb1[c * 64 + j];
#pragma unroll
        for (int i = 0; i < 32; i++) s += fw3[c * 32 + i] * fb2[c * 32 + i];
        sh_beff[c] = s + fb3[c];
    }
    __syncthreads();
    if (tid == 0) {
        float C = db2[0];
        for (int j = 0; j < 64; j++) C += dw2[j] * db1[j];
        for (int c = 0; c < 64; c++) C += g_u[c] * sh_beff[c];
        g_C0[0] = C;
    }
}

// ============================================================================
// main: thread = (channel c, batch pair). Packed f32x2: lo = sample 2p, hi = 2p+1.
// Block = 128 threads = 2 pairs x 64 channels -> 4 samples per block.
// ============================================================================
__global__ __launch_bounds__(128, 2) void mtscnn_main(const float* __restrict__ x,
                                                      float* __restrict__ out) {
    const int c  = threadIdx.x & 63;
    const int pl = threadIdx.x >> 6;                      // which pair in block
    const long long pairIdx = (long long)blockIdx.x * 2 + pl;
    const size_t base = (size_t)pairIdx * 2048 + c;       // 1024 floats per sample

    const u64 C05 = pk2(0.05f, 0.05f);

    // ---- load input taps (t[14..15] dead after pool-trim analysis) ----
    u64 t[14];
#pragma unroll
    for (int i = 0; i < 14; i++) {
        float lo = x[base + i * 64];
        float hi = x[base + 1024 + i * 64];
        t[i] = pk2(lo, hi);
    }

    // ---- conv1 (K=3, valid) + fused leaky+maxpool2: pooled outputs 0..5 ----
    u64 p1[8][6];
#pragma unroll
    for (int o = 0; o < 8; o++) {
        float w0 = g_w1t[(o * 3 + 0) * 64 + c];
        float w1 = g_w1t[(o * 3 + 1) * 64 + c];
        float w2 = g_w1t[(o * 3 + 2) * 64 + c];
        float bb = g_b1t[o * 64 + c];
        u64 W0 = pk2(w0, w0), W1 = pk2(w1, w1), W2 = pk2(w2, w2), BB = pk2(bb, bb);
#pragma unroll
        for (int j = 0; j < 6; j++) {
            u64 hA = ffma2(W0, t[2 * j],     ffma2(W1, t[2 * j + 1], ffma2(W2, t[2 * j + 2], BB)));
            u64 hB = ffma2(W0, t[2 * j + 1], ffma2(W1, t[2 * j + 2], ffma2(W2, t[2 * j + 3], BB)));
            p1[o][j] = lpool2(hA, hB, C05);
        }
    }

    // ---- conv2 (8->16, K=3) + fused leaky+maxpool2 (l=4 dead) + folded dot ----
    float slo = 0.f, shi = 0.f;
#pragma unroll 1
    for (int o2 = 0; o2 < 16; o2++) {
        float bb = g_b2t[o2 * 64 + c];
        u64 BB = pk2(bb, bb);
        u64 a0 = BB, a1 = BB, a2 = BB, a3 = BB;
#pragma unroll
        for (int o = 0; o < 8; o++) {
#pragma unroll
            for (int k = 0; k < 3; k++) {
                float w = g_w2t[((o2 * 8 + o) * 3 + k) * 64 + c];
                u64 W = pk2(w, w);
                a0 = ffma2(W, p1[o][k],     a0);
                a1 = ffma2(W, p1[o][k + 1], a1);
                a2 = ffma2(W, p1[o][k + 2], a2);
                a3 = ffma2(W, p1[o][k + 3], a3);
            }
        }
        u64 q0 = lpool2(a0, a1, C05);
        u64 q1 = lpool2(a2, a3, C05);
        float q0lo, q0hi, q1lo, q1hi;
        upk2(q0, q0lo, q0hi);
        upk2(q1, q1lo, q1hi);
        float Wf0 = g_Wt[(o2 * 2 + 0) * 64 + c];
        float Wf1 = g_Wt[(o2 * 2 + 1) * 64 + c];
        slo = fmaf(q0lo, Wf0, fmaf(q1lo, Wf1, slo));
        shi = fmaf(q0hi, Wf0, fmaf(q1hi, Wf1, shi));
    }

    // ---- reduce over the 64 channels (2 warps per pair) ----
#pragma unroll
    for (int off = 16; off > 0; off >>= 1) {
        slo += __shfl_down_sync(0xffffffffu, slo, off);
        shi += __shfl_down_sync(0xffffffffu, shi, off);
    }
    __shared__ float red[4][2];
    int w = threadIdx.x >> 5;
    if ((threadIdx.x & 31) == 0) {
        red[w][0] = slo;
        red[w][1] = shi;
    }
    __syncthreads();
    if ((threadIdx.x & 63) == 0) {
        float C0 = g_C0[0];
        long long b0 = pairIdx * 2;
        out[b0]     = red[pl * 2][0] + red[pl * 2 + 1][0] + C0;
        out[b0 + 1] = red[pl * 2][1] + red[pl * 2 + 1][1] + C0;
    }
}

// ============================================================================
// launch
// ============================================================================
extern "C" void kernel_launch(void* const* d_in, const int* in_sizes, int n_in,
                              void* d_out, int out_size) {
    const float* x   = (const float*)d_in[0];
    const float* w1  = (const float*)d_in[1];
    const float* b1  = (const float*)d_in[2];
    const float* w2  = (const float*)d_in[3];
    const float* b2  = (const float*)d_in[4];
    const float* fw1 = (const float*)d_in[5];
    const float* fb1 = (const float*)d_in[6];
    const float* fw2 = (const float*)d_in[7];
    const float* fb2 = (const float*)d_in[8];
    const float* fw3 = (const float*)d_in[9];
    const float* fb3 = (const float*)d_in[10];
    const float* dw1 = (const float*)d_in[11];
    const float* db1 = (const float*)d_in[12];
    const float* dw2 = (const float*)d_in[13];
    const float* db2 = (const float*)d_in[14];
    float* out = (float*)d_out;

    mtscnn_pre1<<<125, 256>>>(w1, b1, w2, b2, fw2, fw3, dw1, dw2);
    mtscnn_pre2<<<1, 1024>>>(fw1, fb1, fb2, fb3, fw3, db1, dw2, db2);

    int B = in_sizes[0] / 1024;          // 32768 (x is [B,1,16,8,8])
    int nPairs = B / 2;                  // 2 samples per thread
    int nBlocks = nPairs / 2;            // 2 pairs per 128-thread block
    mtscnn_main<<<nBlocks, 128>>>(x, out);
}

// round 6
// speedup vs baseline: 1.0480x; 1.0456x over previous
#include <cuda_runtime.h>
#include <cstdint>

// ============================================================================
// MTSCNN: 64 per-channel conv extractors + folded linear tail.
// R6: scalar fp32 (f32x2 proved throughput-neutral on sm_100a), with
//  * Winograd F(4,3) for conv2: output positions 0..3 from p1[0..5] is exactly
//    one F(4,3) tile. 48 FFMA/(o2,sample) in transform domain vs 96 direct.
//    Input transform shared across the 16 o2; weight transform G@w2 in pre1.
//  * leaky/pool monotonicity fusion: max(leaky(a),leaky(b)) = leaky(max(a,b)).
//  * 4 samples per thread: each weight load feeds 4 FFMAs (LSU de-bound).
//  * __ldcg on x so the streamed input bypasses L1; weight set stays resident.
// Folded linear tail (validated 2.4e-7): FC(32->64->32->1) + head(64->64->1)
// collapse to W[64x32] + scalar C0.
// ============================================================================

__device__ __forceinline__ float leaky(float v) { return fmaxf(v, 0.05f * v); }

// ---- precomputed / repacked parameter storage (channel-last) ----
__device__ float g_w1t[24 * 64];    // [(o*3+k)*64 + c]
__device__ float g_b1t[8 * 64];     // [o*64 + c]
__device__ float g_gt[768 * 64];    // [((o2*8+o)*6+i)*64 + c]  Winograd G@w2
__device__ float g_b2t[16 * 64];    // [o2*64 + c]
__device__ float g_Wt[32 * 64];     // [f*64 + c]  folded linear tail
__device__ float g_r2[64 * 64];     // scratch: fw3_c @ fw2_c
__device__ float g_u[64];           // dw2 @ dw1
__device__ float g_C0[1];

// ============================================================================
// pre1: repack conv1 weights channel-last; Winograd-transform conv2 weights;
// compute r2[c][j] and u[c].
// Segments: r2 4096 | u 64 | w1t 1536 | b1t 512 | b2t 1024 | gt 49152 = 56384
// ============================================================================
__global__ void mtscnn_pre1(const float* __restrict__ w1, const float* __restrict__ b1,
                            const float* __restrict__ w2, const float* __restrict__ b2,
                            const float* __restrict__ fw2, const float* __restrict__ fw3,
                            const float* __restrict__ dw1, const float* __restrict__ dw2) {
    int tid = blockIdx.x * blockDim.x + threadIdx.x;
    if (tid < 4096) {
        int c = tid >> 6, j = tid & 63;
        float s = 0.f;
#pragma unroll
        for (int i = 0; i < 32; i++)
            s += fw3[c * 32 + i] * fw2[c * 2048 + i * 64 + j];
        g_r2[c * 64 + j] = s;
    } else if (tid < 4160) {
        int c = tid - 4096;
        float s = 0.f;
#pragma unroll
        for (int j = 0; j < 64; j++) s += dw2[j] * dw1[j * 64 + c];
        g_u[c] = s;
    } else if (tid < 5696) {
        int i = tid - 4160;            // i = c*24 + (o*3+k)
        int c = i / 24, r = i % 24;
        g_w1t[r * 64 + c] = w1[i];
    } else if (tid < 6208) {
        int i = tid - 5696;            // i = c*8 + o
        int c = i >> 3, o = i & 7;
        g_b1t[o * 64 + c] = b1[i];
    } else if (tid < 7232) {
        int i = tid - 6208;            // i = c*16 + o2
        int c = i >> 4, o2 = i & 15;
        g_b2t[o2 * 64 + c] = b2[i];
    } else if (tid < 7232 + 49152) {
        int i = tid - 7232;            // i = c*768 + (o2o*6 + irow)
        int c = i / 768, r = i % 768;
        int o2o = r / 6, irow = r % 6;
        const float* g = w2 + c * 384 + o2o * 3;
        float g0 = g[0], g1 = g[1], g2 = g[2];
        float v;
        // G (F(4,3)): [1/4,0,0; -1/6,-1/6,-1/6; -1/6,1/6,-1/6;
        //              1/24,1/12,1/6; 1/24,-1/12,1/6; 0,0,1]
        switch (irow) {
            case 0: v = 0.25f * g0; break;
            case 1: v = -(g0 + g1 + g2) * (1.f / 6.f); break;
            case 2: v = (-g0 + g1 - g2) * (1.f / 6.f); break;
            case 3: v = (g0 + 2.f * g1 + 4.f * g2) * (1.f / 24.f); break;
            case 4: v = (g0 - 2.f * g1 + 4.f * g2) * (1.f / 24.f); break;
            default: v = g2; break;
        }
        g_gt[r * 64 + c] = v;
    }
}

// ============================================================================
// pre2: fold the linear tail (unchanged, validated).
// ============================================================================
__global__ void mtscnn_pre2(const float* __restrict__ fw1, const float* __restrict__ fb1,
                            const float* __restrict__ fb2, const float* __restrict__ fb3,
                            const float* __restrict__ fw3,
                            const float* __restrict__ db1, const float* __restrict__ dw2,
                            const float* __restrict__ db2) {
    __shared__ float sh_beff[64];
    int tid = threadIdx.x;
    for (int e = tid; e < 2048; e += blockDim.x) {
        int c = e >> 5, f = e & 31;
        float s = 0.f;
#pragma unroll
        for (int j = 0; j < 64; j++)
            s += g_r2[c * 64 + j] * fw1[c * 2048 + j * 32 + f];
        g_Wt[f * 64 + c] = g_u[c] * s;
    }
    if (tid < 64) {
        int c = tid;
        float s = 0.f;
#pragma unroll
        for (int j = 0; j < 64; j++) s += g_r2[c * 64 + j] * fb1[c * 64 + j];
#pragma unroll
        for (int i = 0; i < 32; i++) s += fw3[c * 32 + i] * fb2[c * 32 + i];
        sh_beff[c] = s + fb3[c];
    }
    __syncthreads();
    if (tid == 0) {
        float C = db2[0];
        for (int j = 0; j < 64; j++) C += dw2[j] * db1[j];
        for (int c = 0; c < 64; c++) C += g_u[c] * sh_beff[c];
        g_C0[0] = C;
    }
}

// ============================================================================
// main: thread = (channel c, 4 samples). Block = 128 threads = 2 groups x 64 c
// -> 8 samples per block.
// ============================================================================
__global__ __launch_bounds__(128, 2) void mtscnn_main(const float* __restrict__ x,
                                                      float* __restrict__ out) {
    const int c   = threadIdx.x & 63;
    const int grp = threadIdx.x >> 6;
    const long long q = (long long)blockIdx.x * 2 + grp;   // 4-sample group
    const float* xb = x + (size_t)q * 4096 + c;

    // Phase 1: conv1 + pool + leaky, then Winograd input transform -> dt
    float dt[4 * 48];                                      // [s][o*6 + i]
#pragma unroll
    for (int s = 0; s < 4; s++) {
        float t[14];                                       // taps 14,15 dead
#pragma unroll
        for (int i = 0; i < 14; i++) t[i] = __ldcg(xb + (size_t)s * 1024 + i * 64);
#pragma unroll
        for (int o = 0; o < 8; o++) {
            float w0 = g_w1t[(o * 3 + 0) * 64 + c];
            float w1 = g_w1t[(o * 3 + 1) * 64 + c];
            float w2v = g_w1t[(o * 3 + 2) * 64 + c];
            float bb = g_b1t[o * 64 + c];
            float p[6];
#pragma unroll
            for (int j = 0; j < 6; j++) {
                float hA = fmaf(w0, t[2 * j],     fmaf(w1, t[2 * j + 1], fmaf(w2v, t[2 * j + 2], bb)));
                float hB = fmaf(w0, t[2 * j + 1], fmaf(w1, t[2 * j + 2], fmaf(w2v, t[2 * j + 3], bb)));
                p[j] = leaky(fmaxf(hA, hB));               // leaky(max) == max(leaky)
            }
            // B^T d  (F(4,3), points 0,±1,±2,inf)
            float pq = p[1] + p[2], qq = p[3] + p[4];
            float ss = p[1] - p[2], tt = p[4] - p[3];
            float uu = p[3] - p[1], vv = p[4] - p[2];
            float* d = dt + s * 48 + o * 6;
            d[0] = fmaf(4.f, p[0], fmaf(-5.f, p[2], p[4]));
            d[1] = fmaf(-4.f, pq, qq);
            d[2] = fmaf(4.f, ss, tt);
            d[3] = fmaf(2.f, uu, vv);
            d[4] = fmaf(-2.f, uu, vv);
            d[5] = fmaf(4.f, p[1], fmaf(-5.f, p[3], p[5]));
        }
    }

    // Phase 2: conv2 in Winograd domain + output transform + leaky/pool + dot
    float acc[4] = {0.f, 0.f, 0.f, 0.f};
#pragma unroll 1
    for (int o2 = 0; o2 < 16; o2++) {
        float m[24];
#pragma unroll
        for (int k = 0; k < 24; k++) m[k] = 0.f;
#pragma unroll
        for (int o = 0; o < 8; o++) {
#pragma unroll
            for (int i = 0; i < 6; i++) {
                float g = g_gt[((o2 * 8 + o) * 6 + i) * 64 + c];
#pragma unroll
                for (int s = 0; s < 4; s++)
                    m[s * 6 + i] = fmaf(g, dt[s * 48 + o * 6 + i], m[s * 6 + i]);
            }
        }
        float bb  = g_b2t[o2 * 64 + c];
        float Wf0 = g_Wt[(o2 * 2 + 0) * 64 + c];
        float Wf1 = g_Wt[(o2 * 2 + 1) * 64 + c];
#pragma unroll
        for (int s = 0; s < 4; s++) {
            float m0 = m[s * 6], m1 = m[s * 6 + 1], m2 = m[s * 6 + 2];
            float m3 = m[s * 6 + 3], m4 = m[s * 6 + 4], m5 = m[s * 6 + 5];
            float s1 = m1 + m2, s2 = m1 - m2, t1 = m3 + m4, t2 = m3 - m4;
            float y0 = (m0 + s1) + (t1 + bb);
            float y1 = fmaf(2.f, t2, s2) + bb;
            float y2 = fmaf(4.f, t1, s1) + bb;
            float y3 = fmaf(8.f, t2, s2 + m5) + bb;
            float q0 = leaky(fmaxf(y0, y1));               // pool pos {0,1}
            float q1 = leaky(fmaxf(y2, y3));               // pool pos {2,3}
            acc[s] = fmaf(q0, Wf0, fmaf(q1, Wf1, acc[s]));
        }
    }

    // reduce over the 64 channels (2 warps per group)
#pragma unroll
    for (int off = 16; off > 0; off >>= 1) {
#pragma unroll
        for (int s = 0; s < 4; s++)
            acc[s] += __shfl_down_sync(0xffffffffu, acc[s], off);
    }
    __shared__ float red[4][4];
    int w = threadIdx.x >> 5;
    if ((threadIdx.x & 31) == 0) {
#pragma unroll
        for (int s = 0; s < 4; s++) red[w][s] = acc[s];
    }
    __syncthreads();
    if ((threadIdx.x & 63) == 0) {
        float C0 = g_C0[0];
        long long b0 = q * 4;
#pragma unroll
        for (int s = 0; s < 4; s++)
            out[b0 + s] = red[grp * 2][s] + red[grp * 2 + 1][s] + C0;
    }
}

// ============================================================================
// launch
// ============================================================================
extern "C" void kernel_launch(void* const* d_in, const int* in_sizes, int n_in,
                              void* d_out, int out_size) {
    const float* x   = (const float*)d_in[0];
    const float* w1  = (const float*)d_in[1];
    const float* b1  = (const float*)d_in[2];
    const float* w2  = (const float*)d_in[3];
    const float* b2  = (const float*)d_in[4];
    const float* fw1 = (const float*)d_in[5];
    const float* fb1 = (const float*)d_in[6];
    const float* fw2 = (const float*)d_in[7];
    const float* fb2 = (const float*)d_in[8];
    const float* fw3 = (const float*)d_in[9];
    const float* fb3 = (const float*)d_in[10];
    const float* dw1 = (const float*)d_in[11];
    const float* db1 = (const float*)d_in[12];
    const float* dw2 = (const float*)d_in[13];
    const float* db2 = (const float*)d_in[14];
    float* out = (float*)d_out;

    mtscnn_pre1<<<221, 256>>>(w1, b1, w2, b2, fw2, fw3, dw1, dw2);   // 56384 items
    mtscnn_pre2<<<1, 1024>>>(fw1, fb1, fb2, fb3, fw3, db1, dw2, db2);

    int B = in_sizes[0] / 1024;      // 32768
    int nBlocks = B / 8;             // 8 samples per block (2 groups x 4)
    mtscnn_main<<<nBlocks, 128>>>(x, out);
}